// round 1
// baseline (speedup 1.0000x reference)
#include <cuda_runtime.h>
#include <cstdint>
#include <math.h>

// Problem constants
#define CH   256      // CHAR_HID
#define CE   128      // CHAR_EMB
#define WH   512      // WORD_HID
#define WE   512      // WORD_EMB
#define T16  16       // CHAR_LEN
#define NTAG 50

// ---------------- scratch (no allocations allowed) ----------------
__device__ __align__(16) float g_xb[T16 * 4 * CH];   // [16][1024] x-part + bias of char gates
__device__ __align__(16) float g_we[WE];             // gathered word embedding
__device__ __align__(16) float g_charh[CH];          // final char hidden
__device__ __align__(16) float g_hword[WH];          // word LSTM hidden
__device__ int g_ctr = 0;

__device__ __forceinline__ float sigmoidf_(float x) {
    return 1.f / (1.f + __expf(-x));
}

// =====================================================================
// K0: prep — xb[t][row] = dot(char_w_ih[row], char_emb[cs[t]]) + b_ih + b_hh
//     plus gather word embedding row.
// grid 65 x 256
// =====================================================================
__global__ __launch_bounds__(256) void prep_kernel(
    const int* __restrict__ wseq, const int* __restrict__ cseq,
    const float* __restrict__ word_emb, const float* __restrict__ char_emb,
    const float* __restrict__ cwih, const float* __restrict__ cbih,
    const float* __restrict__ cbhh)
{
    int tid = threadIdx.x;
    if (blockIdx.x == 64) {
        // gather word embedding
        int w = wseq[0];
        const float* src = word_emb + (size_t)w * WE;
        for (int i = tid; i < WE; i += 256) g_we[i] = src[i];
        return;
    }
    __shared__ float ce_s[T16][CE + 4];
    __shared__ float w_s[16][CE + 4];
    __shared__ int cs_s[T16];
    if (tid < T16) cs_s[tid] = cseq[tid];
    __syncthreads();
    // stage char embeddings for all 16 timesteps
    for (int i = tid; i < T16 * CE; i += 256) {
        int r = i >> 7, c = i & 127;
        ce_s[r][c] = char_emb[(size_t)cs_s[r] * CE + c];
    }
    // stage 16 rows of char_w_ih for this block
    int rbase = blockIdx.x * 16;
    for (int i = tid; i < 16 * CE; i += 256) {
        int r = i >> 7, c = i & 127;
        w_s[r][c] = cwih[(size_t)(rbase + r) * CE + c];
    }
    __syncthreads();
    // thread (t, r) computes one output
    int t = tid >> 4, r = tid & 15;
    const float4* w4 = (const float4*)&w_s[r][0];
    const float4* c4 = (const float4*)&ce_s[t][0];
    float acc = 0.f;
#pragma unroll
    for (int k = 0; k < CE / 4; k++) {
        float4 a = w4[k], b = c4[k];
        acc += a.x * b.x; acc += a.y * b.y; acc += a.z * b.z; acc += a.w * b.w;
    }
    int grow = rbase + r;
    g_xb[t * 1024 + grow] = acc + cbih[grow] + cbhh[grow];
}

// =====================================================================
// K1: char LSTM recurrence — one 8-CTA cluster.
// CTA r owns h indices [32r, 32r+32): 128 gate rows of char_w_hh,
// kept in registers (2 threads per row, 128 floats each).
// Per step: reg-dot against SMEM h, pair-shfl reduce, 32 threads do
// activations + DSMEM broadcast of new h to all 8 CTAs, cluster sync.
// =====================================================================
__global__ void __cluster_dims__(8, 1, 1) __launch_bounds__(256, 1)
char_lstm_kernel(const float* __restrict__ cwhh)
{
    __shared__ float h0[CH];
    __shared__ float h1[CH];
    __shared__ float gates_s[128];
    __shared__ float xb_s[T16 * 128];
    __shared__ float stage[32 * 260];   // 32 rows, padded stride 260 floats

    int tid  = threadIdx.x;
    int rank = blockIdx.x;              // single cluster -> blockIdx == cluster rank
    int lrow = tid >> 1;                // 0..127  (gate = lrow>>5, j = lrow&31)
    int half = tid & 1;                 // which 128-wide half of the 256-dot

    // zero h0 (initial hidden). h1 fully overwritten by step-0 broadcast.
    h0[tid] = 0.f;

    // load this CTA's xb slice: xb_s[t*128 + lrow]
    for (int i = tid; i < T16 * 128; i += 256) {
        int t = i >> 7, l = i & 127;
        int grow = ((l >> 5) << 8) + (rank << 5) + (l & 31);
        xb_s[i] = g_xb[t * 1024 + grow];
    }

    // load 128 gate rows of w_hh into registers via 4 staged chunks
    float w[128];
#pragma unroll 1
    for (int cch = 0; cch < 4; cch++) {
        // coalesced stage of 32 rows (each 256 floats) as float4
        for (int i = tid; i < 32 * 64; i += 256) {
            int lr = i >> 6, k4 = i & 63;
            int l = cch * 32 + lr;
            int grow = ((l >> 5) << 8) + (rank << 5) + (l & 31);
            *(float4*)&stage[lr * 260 + 4 * k4] =
                *(const float4*)&cwhh[(size_t)grow * 256 + 4 * k4];
        }
        __syncthreads();
        if ((lrow >> 5) == cch) {
            const float* src = &stage[(lrow & 31) * 260 + half * 128];
#pragma unroll
            for (int i = 0; i < 128; i++) w[i] = src[i];
        }
        __syncthreads();
    }

    float c = 0.f;  // cell state, meaningful only for tid < 32

#pragma unroll 1
    for (int t = 0; t < T16; t++) {
        const float* hp = (t & 1) ? h1 : h0;   // h_{t-1}
        float* hn       = (t & 1) ? h0 : h1;   // h_t destination

        float acc = 0.f;
        const float4* h4 = (const float4*)(hp + (half << 7));
#pragma unroll
        for (int k = 0; k < 32; k++) {
            float4 hv = h4[k];
            acc += w[4 * k + 0] * hv.x;
            acc += w[4 * k + 1] * hv.y;
            acc += w[4 * k + 2] * hv.z;
            acc += w[4 * k + 3] * hv.w;
        }
        acc += __shfl_xor_sync(0xffffffffu, acc, 1);
        if (half == 0) gates_s[lrow] = acc + xb_s[(t << 7) + lrow];
        __syncthreads();

        if (tid < 32) {
            float gi = gates_s[tid];
            float gf = gates_s[32 + tid];
            float gg = gates_s[64 + tid];
            float go = gates_s[96 + tid];
            float iv = sigmoidf_(gi);
            float fv = sigmoidf_(gf);
            float gv = tanhf(gg);
            float ov = sigmoidf_(go);
            c = fv * c + iv * gv;
            float h = ov * tanhf(c);
            // broadcast h[32*rank + tid] to all 8 CTAs' hn buffer
            uint32_t a_local =
                (uint32_t)__cvta_generic_to_shared(&hn[(rank << 5) + tid]);
#pragma unroll
            for (int r = 0; r < 8; r++) {
                uint32_t ra;
                asm volatile("mapa.shared::cluster.u32 %0, %1, %2;"
                             : "=r"(ra) : "r"(a_local), "r"(r));
                asm volatile("st.shared::cluster.f32 [%0], %1;"
                             :: "r"(ra), "f"(h) : "memory");
            }
        }
        // release(writes) -> barrier -> acquire on all CTAs
        asm volatile("barrier.cluster.arrive.aligned;" ::: "memory");
        asm volatile("barrier.cluster.wait.aligned;" ::: "memory");
    }

    // after 16 steps, h_16 lives in h0 (t=15 wrote hn=h0)
    if (rank == 0) g_charh[tid] = h0[tid];
}

// =====================================================================
// K2: word LSTM single step (h_prev = 0 -> only i,g,o gates; no W_hh)
//     + tag head + log_softmax by the last-finishing block.
// grid 64 x 256, one warp per h_word output.
// =====================================================================
__global__ __launch_bounds__(256) void word_kernel(
    const float* __restrict__ wwih, const float* __restrict__ wbih,
    const float* __restrict__ wbhh, const float* __restrict__ tagw,
    const float* __restrict__ tagb, float* __restrict__ out)
{
    __shared__ int lastf;
    __shared__ float logit_s[64];
    if (threadIdx.x == 0) lastf = 0;
    __syncthreads();

    int warp = threadIdx.x >> 5, lane = threadIdx.x & 31;
    int j = blockIdx.x * 8 + warp;   // 0..511

    const float4* ri = (const float4*)(wwih + (size_t)j * 768);
    const float4* rg = (const float4*)(wwih + (size_t)(1024 + j) * 768);
    const float4* ro = (const float4*)(wwih + (size_t)(1536 + j) * 768);
    const float4* we4 = (const float4*)g_we;      // 128 float4
    const float4* ch4 = (const float4*)g_charh;   // 64 float4

    float ai = 0.f, ag = 0.f, ao = 0.f;
#pragma unroll
    for (int cc = 0; cc < 6; cc++) {
        int idx = cc * 32 + lane;
        float4 x = (cc < 4) ? we4[idx] : ch4[idx - 128];
        float4 a = ri[idx], b = rg[idx], d = ro[idx];
        ai += a.x * x.x; ai += a.y * x.y; ai += a.z * x.z; ai += a.w * x.w;
        ag += b.x * x.x; ag += b.y * x.y; ag += b.z * x.z; ag += b.w * x.w;
        ao += d.x * x.x; ao += d.y * x.y; ao += d.z * x.z; ao += d.w * x.w;
    }
#pragma unroll
    for (int s = 16; s; s >>= 1) {
        ai += __shfl_xor_sync(0xffffffffu, ai, s);
        ag += __shfl_xor_sync(0xffffffffu, ag, s);
        ao += __shfl_xor_sync(0xffffffffu, ao, s);
    }
    if (lane == 0) {
        float iv = sigmoidf_(ai + wbih[j] + wbhh[j]);
        float gv = tanhf(ag + wbih[1024 + j] + wbhh[1024 + j]);
        float ov = sigmoidf_(ao + wbih[1536 + j] + wbhh[1536 + j]);
        float cc = iv * gv;                      // f*c_prev = 0
        g_hword[j] = ov * tanhf(cc);
        __threadfence();
        int old = atomicAdd(&g_ctr, 1);
        if (old == 511) lastf = 1;               // I'm the global last warp
    }
    __syncthreads();
    if (!lastf) return;
    __threadfence();                             // acquire all g_hword writes

    // ---- tag head: 50 outputs, warp per output ----
    const float4* hw4 = (const float4*)g_hword;  // 128 float4
    for (int o = warp; o < NTAG; o += 8) {
        const float4* tw = (const float4*)(tagw + (size_t)o * WH);
        float acc = 0.f;
#pragma unroll
        for (int cc = 0; cc < 4; cc++) {
            int idx = cc * 32 + lane;
            float4 a = tw[idx], x = hw4[idx];
            acc += a.x * x.x; acc += a.y * x.y; acc += a.z * x.z; acc += a.w * x.w;
        }
#pragma unroll
        for (int s = 16; s; s >>= 1) acc += __shfl_xor_sync(0xffffffffu, acc, s);
        if (lane == 0) logit_s[o] = acc + tagb[o];
    }
    __syncthreads();
    if (threadIdx.x == 0) {
        float m = -1e30f;
        for (int i = 0; i < NTAG; i++) m = fmaxf(m, logit_s[i]);
        float s = 0.f;
        for (int i = 0; i < NTAG; i++) s += expf(logit_s[i] - m);
        float ls = logf(s) + m;
        for (int i = 0; i < NTAG; i++) out[i] = logit_s[i] - ls;
        g_ctr = 0;   // reset for next (graph-replayed) launch
    }
}

// =====================================================================
extern "C" void kernel_launch(void* const* d_in, const int* in_sizes, int n_in,
                              void* d_out, int out_size)
{
    const int*   wseq     = (const int*)  d_in[0];
    const int*   cseq     = (const int*)  d_in[1];
    const float* word_emb = (const float*)d_in[2];
    const float* char_emb = (const float*)d_in[3];
    const float* cwih     = (const float*)d_in[4];
    const float* cwhh     = (const float*)d_in[5];
    const float* cbih     = (const float*)d_in[6];
    const float* cbhh     = (const float*)d_in[7];
    const float* wwih     = (const float*)d_in[8];
    /* d_in[9] = word_w_hh: provably unused (seq len 1, zero init) */
    const float* wbih     = (const float*)d_in[10];
    const float* wbhh     = (const float*)d_in[11];
    const float* tagw     = (const float*)d_in[12];
    const float* tagb     = (const float*)d_in[13];
    float* out = (float*)d_out;

    prep_kernel<<<65, 256>>>(wseq, cseq, word_emb, char_emb, cwih, cbih, cbhh);
    char_lstm_kernel<<<8, 256>>>(cwhh);
    word_kernel<<<64, 256>>>(wwih, wbih, wbhh, tagw, tagb, out);
}

// round 4
// speedup vs baseline: 1.1061x; 1.1061x over previous
#include <cuda_runtime.h>
#include <cstdint>

#define T16  16
#define NTAG 50
#define SPIN_MAX (1 << 24)   // bounded spin: converts any deadlock into a fast wrong answer

// ---------------- device scratch (no allocations allowed) ----------------
__device__ __align__(16) float g_xb[16 * 1024];   // [t][gate-row] x-part + bias
__device__ __align__(16) float g_charh[256];      // final char hidden
__device__ __align__(16) float g_hword[512];      // word LSTM hidden
__device__ int g_xbcnt = 0;
__device__ int g_chcnt = 0;
__device__ int g_wcnt  = 0;

__device__ __forceinline__ float sigf(float x)  { return __fdividef(1.f, 1.f + __expf(-x)); }
__device__ __forceinline__ float tanh_(float x) { return __fdividef(2.f, 1.f + __expf(-2.f * x)) - 1.f; }

// =====================================================================
// Single fused kernel. Grid 64 x 256, clusters of 8.
//   CTAs 0-7  (cluster 0): char LSTM recurrence (w_hh in registers, f32x2)
//   CTAs 8-63 : xb prep (64 chunks of 16 gate rows), then word LSTM
//               (warp per output j, two phases), then elected tag head.
// =====================================================================
__global__ void __cluster_dims__(8, 1, 1) __launch_bounds__(256, 1)
fused(const int* __restrict__ wseq, const int* __restrict__ cseq,
      const float* __restrict__ word_emb, const float* __restrict__ char_emb,
      const float* __restrict__ cwih, const float* __restrict__ cwhh,
      const float* __restrict__ cbih, const float* __restrict__ cbhh,
      const float* __restrict__ wwih, const float* __restrict__ wbih,
      const float* __restrict__ wbhh, const float* __restrict__ tagw,
      const float* __restrict__ tagb, float* __restrict__ out)
{
    __shared__ __align__(16) float smem[4352];
    __shared__ int cs_s[16];
    __shared__ int flag;

    const int tid = threadIdx.x;
    const int bx  = blockIdx.x;

    // =================================================================
    // cluster 0: char LSTM
    // =================================================================
    if (bx < 8) {
        float* h0  = smem;          // 256
        float* h1  = smem + 256;    // 256
        float* act = smem + 512;    // 128
        float* xb  = smem + 640;    // 2048
        const int rank = bx;
        const int lrow = tid >> 1;          // 0..127
        const int half = tid & 1;
        const int gate = lrow >> 5;
        const int grow = (gate << 8) + (rank << 5) + (lrow & 31);

        // ---- w_hh rows -> registers, packed as f32x2 pairs ----
        unsigned long long w2[64];
        {
            const ulonglong2* wsrc =
                (const ulonglong2*)(cwhh + (size_t)grow * 256 + (half << 7));
#pragma unroll
            for (int k = 0; k < 32; k++) {
                ulonglong2 v = __ldg(wsrc + k);
                w2[2 * k] = v.x; w2[2 * k + 1] = v.y;
            }
        }
        h0[tid] = 0.f;

        // ---- DSMEM broadcast addresses ----
        uint32_t ra0[8], ra1[8];
        if (tid < 32) {
            uint32_t a0 = (uint32_t)__cvta_generic_to_shared(&h0[(rank << 5) + tid]);
            uint32_t a1 = (uint32_t)__cvta_generic_to_shared(&h1[(rank << 5) + tid]);
#pragma unroll
            for (int r = 0; r < 8; r++) {
                asm("mapa.shared::cluster.u32 %0,%1,%2;" : "=r"(ra0[r]) : "r"(a0), "r"(r));
                asm("mapa.shared::cluster.u32 %0,%1,%2;" : "=r"(ra1[r]) : "r"(a1), "r"(r));
            }
        }

        // ---- wait (bounded) for xb from prep CTAs, then stage slice ----
        if (tid == 0) {
            int it = 0;
            while (*(volatile int*)&g_xbcnt < 56 && it++ < SPIN_MAX) __nanosleep(64);
            __threadfence();
        }
        __syncthreads();
        for (int i = tid; i < 2048; i += 256) {
            int t = i >> 7, l = i & 127;
            xb[i] = g_xb[(t << 10) + ((l >> 5) << 8) + (rank << 5) + (l & 31)];
        }
        __syncthreads();

        float c = 0.f;
#pragma unroll 1
        for (int t = 0; t < T16; t++) {
            const float* hp = (t & 1) ? h1 : h0;
            float xbv = xb[(t << 7) + lrow];          // prefetch gate bias+x part
            unsigned long long acc_a = 0ull, acc_b = 0ull;
            const ulonglong2* h2 = (const ulonglong2*)(hp + (half << 7));
#pragma unroll
            for (int k = 0; k < 32; k++) {
                ulonglong2 hv = h2[k];
                asm("fma.rn.f32x2 %0,%1,%2,%0;" : "+l"(acc_a) : "l"(w2[2 * k]),     "l"(hv.x));
                asm("fma.rn.f32x2 %0,%1,%2,%0;" : "+l"(acc_b) : "l"(w2[2 * k + 1]), "l"(hv.y));
            }
            float s0, s1, s2, s3;
            asm("mov.b64 {%0,%1},%2;" : "=f"(s0), "=f"(s1) : "l"(acc_a));
            asm("mov.b64 {%0,%1},%2;" : "=f"(s2), "=f"(s3) : "l"(acc_b));
            float acc = (s0 + s2) + (s1 + s3);
            acc += __shfl_xor_sync(0xffffffffu, acc, 1);
            if (half == 0) {
                float v = acc + xbv;
                act[lrow] = (gate == 2) ? tanh_(v) : sigf(v);
            }
            __syncthreads();
            if (tid < 32) {
                float iv = act[tid],      fv = act[32 + tid];
                float gv = act[64 + tid], ov = act[96 + tid];
                c = fmaf(fv, c, iv * gv);
                float h = ov * tanh_(c);
                if (t < 15) {
#pragma unroll
                    for (int r = 0; r < 8; r++) {
                        uint32_t ad = (t & 1) ? ra0[r] : ra1[r];
                        asm volatile("st.shared::cluster.f32 [%0],%1;"
                                     :: "r"(ad), "f"(h) : "memory");
                    }
                } else {
                    g_charh[(rank << 5) + tid] = h;
                }
            }
            if (t < 15) {
                asm volatile("barrier.cluster.arrive.aligned;" ::: "memory");
                asm volatile("barrier.cluster.wait.aligned;"   ::: "memory");
            }
        }
        if (tid < 32) {
            __syncwarp();            // memory-ordering point for the 32 g_charh stores
            __threadfence();
            if (tid == 0) atomicAdd(&g_chcnt, 1);   // target 8
        }
        return;
    }

    // =================================================================
    // CTAs 8-63: xb prep, then word LSTM, then elected tag head
    // =================================================================
    float* ce    = smem;          // 16*132
    float* ws    = smem + 2112;   // 16*132
    float* logit = smem + 4224;   // 64

    const int lane = tid & 31, warp = tid >> 5;
    const int c0 = bx - 8;        // 0..55

    if (tid == 0) flag = 0;
    if (tid < 16) cs_s[tid] = cseq[tid];
    __syncthreads();

    // stage char embeddings for all 16 timesteps (float4)
    for (int i = tid; i < 512; i += 256) {
        int r = i >> 5, q = i & 31;
        *(float4*)(ce + r * 132 + 4 * q) =
            __ldg((const float4*)(char_emb + (size_t)cs_s[r] * 128) + q);
    }

    // ---- xb chunks: primary c0; CTAs 8-15 also take c0+56 ----
    const int nch = (c0 < 8) ? 2 : 1;
    for (int p = 0; p < nch; p++) {
        int ch = (p == 0) ? c0 : c0 + 56;
        int rbase = ch * 16;
        for (int i = tid; i < 512; i += 256) {
            int r = i >> 5, q = i & 31;
            *(float4*)(ws + r * 132 + 4 * q) =
                __ldg((const float4*)(cwih + (size_t)(rbase + r) * 128) + q);
        }
        __syncthreads();
        {
            int t = tid >> 4, r = tid & 15;
            const float4* w4 = (const float4*)(ws + r * 132);
            const float4* c4 = (const float4*)(ce + t * 132);
            float acc = 0.f;
#pragma unroll
            for (int k = 0; k < 32; k++) {
                float4 a = w4[k], b = c4[k];
                acc = fmaf(a.x, b.x, acc); acc = fmaf(a.y, b.y, acc);
                acc = fmaf(a.z, b.z, acc); acc = fmaf(a.w, b.w, acc);
            }
            int grow = rbase + r;
            g_xb[t * 1024 + grow] = acc + cbih[grow] + cbhh[grow];
        }
        __syncthreads();
    }
    if (tid == 0) { __threadfence(); atomicAdd(&g_xbcnt, 1); }   // target 56

    // ---- word LSTM: warp per output j; jobs wg and (wg<64 ? wg+448) ----
    const int wg = c0 * 8 + warp;   // 0..447
    int jl[2]; int nj = 1;
    jl[0] = wg;
    if (wg < 64) { jl[1] = wg + 448; nj = 2; }

    const int widx = __ldg(wseq);
    const float4* xwe = (const float4*)(word_emb + (size_t)widx * 512);  // 128 f4

    // phase 1: cols [0,512) — independent of char LSTM (overlaps recurrence)
    float p1[2][3];
#pragma unroll 1
    for (int p = 0; p < nj; p++) {
        int j = jl[p];
        const float4* ri = (const float4*)wwih + (size_t)j * 192;
        const float4* rg = (const float4*)wwih + (size_t)(1024 + j) * 192;
        const float4* ro = (const float4*)wwih + (size_t)(1536 + j) * 192;
        float ai = 0.f, ag = 0.f, ao = 0.f;
#pragma unroll
        for (int cc = 0; cc < 4; cc++) {
            int idx = cc * 32 + lane;
            float4 x = xwe[idx];
            float4 a = __ldg(ri + idx), b = __ldg(rg + idx), d = __ldg(ro + idx);
            ai = fmaf(a.x, x.x, ai); ai = fmaf(a.y, x.y, ai);
            ai = fmaf(a.z, x.z, ai); ai = fmaf(a.w, x.w, ai);
            ag = fmaf(b.x, x.x, ag); ag = fmaf(b.y, x.y, ag);
            ag = fmaf(b.z, x.z, ag); ag = fmaf(b.w, x.w, ag);
            ao = fmaf(d.x, x.x, ao); ao = fmaf(d.y, x.y, ao);
            ao = fmaf(d.z, x.z, ao); ao = fmaf(d.w, x.w, ao);
        }
        p1[p][0] = ai; p1[p][1] = ag; p1[p][2] = ao;
    }

    // wait (bounded) for char hidden
    if (lane == 0) {
        int it = 0;
        while (*(volatile int*)&g_chcnt < 8 && it++ < SPIN_MAX) __nanosleep(32);
    }
    __syncwarp();
    __threadfence();

    // phase 2: cols [512,768) against g_charh, activations, publish
    const float4* ch4 = (const float4*)g_charh;   // 64 f4
#pragma unroll 1
    for (int p = 0; p < nj; p++) {
        int j = jl[p];
        const float4* ri = (const float4*)wwih + (size_t)j * 192;
        const float4* rg = (const float4*)wwih + (size_t)(1024 + j) * 192;
        const float4* ro = (const float4*)wwih + (size_t)(1536 + j) * 192;
        float ai = p1[p][0], ag = p1[p][1], ao = p1[p][2];
#pragma unroll
        for (int cc = 4; cc < 6; cc++) {
            int idx = cc * 32 + lane;
            float4 x = ch4[idx - 128];
            float4 a = __ldg(ri + idx), b = __ldg(rg + idx), d = __ldg(ro + idx);
            ai = fmaf(a.x, x.x, ai); ai = fmaf(a.y, x.y, ai);
            ai = fmaf(a.z, x.z, ai); ai = fmaf(a.w, x.w, ai);
            ag = fmaf(b.x, x.x, ag); ag = fmaf(b.y, x.y, ag);
            ag = fmaf(b.z, x.z, ag); ag = fmaf(b.w, x.w, ag);
            ao = fmaf(d.x, x.x, ao); ao = fmaf(d.y, x.y, ao);
            ao = fmaf(d.z, x.z, ao); ao = fmaf(d.w, x.w, ao);
        }
#pragma unroll
        for (int s = 16; s; s >>= 1) {
            ai += __shfl_xor_sync(0xffffffffu, ai, s);
            ag += __shfl_xor_sync(0xffffffffu, ag, s);
            ao += __shfl_xor_sync(0xffffffffu, ao, s);
        }
        if (lane == 0) {
            float iv = sigf(ai + wbih[j] + wbhh[j]);
            float gv = tanh_(ag + wbih[1024 + j] + wbhh[1024 + j]);
            float ov = sigf(ao + wbih[1536 + j] + wbhh[1536 + j]);
            g_hword[j] = ov * tanh_(iv * gv);     // c_prev = 0 -> c = i*g
            __threadfence();
            int old = atomicAdd(&g_wcnt, 1);
            if (old == 511) flag = 1;             // last job globally -> this CTA tags
        }
    }
    __syncthreads();
    if (!flag) return;
    __threadfence();

    // ---- tag head + log_softmax (elected CTA only) ----
    const float4* hw4 = (const float4*)g_hword;   // 128 f4
    for (int o = warp; o < NTAG; o += 8) {
        const float4* tw = (const float4*)(tagw + (size_t)o * 512);
        float acc = 0.f;
#pragma unroll
        for (int cc = 0; cc < 4; cc++) {
            int idx = cc * 32 + lane;
            float4 a = __ldg(tw + idx), x = hw4[idx];
            acc = fmaf(a.x, x.x, acc); acc = fmaf(a.y, x.y, acc);
            acc = fmaf(a.z, x.z, acc); acc = fmaf(a.w, x.w, acc);
        }
#pragma unroll
        for (int s = 16; s; s >>= 1) acc += __shfl_xor_sync(0xffffffffu, acc, s);
        if (lane == 0) logit[o] = acc + tagb[o];
    }
    __syncthreads();
    if (tid == 0) {
        float m = -1e30f;
        for (int i = 0; i < NTAG; i++) m = fmaxf(m, logit[i]);
        float s = 0.f;
        for (int i = 0; i < NTAG; i++) s += expf(logit[i] - m);
        float ls = logf(s) + m;
        for (int i = 0; i < NTAG; i++) out[i] = logit[i] - ls;
        g_xbcnt = 0; g_chcnt = 0; g_wcnt = 0;     // reset for graph replay
    }
}

// =====================================================================
extern "C" void kernel_launch(void* const* d_in, const int* in_sizes, int n_in,
                              void* d_out, int out_size)
{
    const int*   wseq     = (const int*)  d_in[0];
    const int*   cseq     = (const int*)  d_in[1];
    const float* word_emb = (const float*)d_in[2];
    const float* char_emb = (const float*)d_in[3];
    const float* cwih     = (const float*)d_in[4];
    const float* cwhh     = (const float*)d_in[5];
    const float* cbih     = (const float*)d_in[6];
    const float* cbhh     = (const float*)d_in[7];
    const float* wwih     = (const float*)d_in[8];
    /* d_in[9] = word_w_hh: provably unused (seq len 1, zero initial state) */
    const float* wbih     = (const float*)d_in[10];
    const float* wbhh     = (const float*)d_in[11];
    const float* tagw     = (const float*)d_in[12];
    const float* tagb     = (const float*)d_in[13];
    float* out = (float*)d_out;

    fused<<<64, 256>>>(wseq, cseq, word_emb, char_emb, cwih, cwhh, cbih, cbhh,
                       wwih, wbih, wbhh, tagw, tagb, out);
}